// round 4
// baseline (speedup 1.0000x reference)
#include <cuda_runtime.h>
#include <math.h>

#define BB 64
#define TT 2048
#define DD 128
#define UU 128
#define G3 384
#define NS 3

// ---------------- scratch (device globals: allocation-free) ----------------
__device__ float  g_GX[(size_t)TT * BB * G3];          // x@kernel + bias   [t][b][384]
__device__ float  g_PX[(size_t)TT * NS * BB * DD];     // x@sub_kernel_x    [t][r=n*64+b2][128]
__device__ float4 g_R4[32 * G3];                       // recurrent_kernel, packed over u (4 at a time)
__device__ float4 g_skh4[NS * 32 * 128];               // sub_kernel_h, packed over o
__device__ float4 g_dw4[NS * 32 * 128];                // dense_w, packed over i
__device__ float4 g_aw4[96 * 128];                     // agg_w, packed over row ko

// ---------------- weight packing: reduction-major float4 layouts -----------
__global__ void pack_weights(const float* __restrict__ R,
                             const float* __restrict__ skh,
                             const float* __restrict__ dw,
                             const float* __restrict__ aw) {
    int idx = blockIdx.x * blockDim.x + threadIdx.x;
    if (idx < 12288) {
        int ug = idx / G3, j = idx % G3;
        g_R4[idx] = make_float4(R[(4*ug+0)*G3 + j], R[(4*ug+1)*G3 + j],
                                R[(4*ug+2)*G3 + j], R[(4*ug+3)*G3 + j]);
    } else if (idx < 24576) {
        int e = idx - 12288;
        int n = e / 4096, rem = e % 4096, og = rem / 128, i = rem % 128;
        const float* p = skh + n * 16384;
        g_skh4[e] = make_float4(p[(4*og+0)*128 + i], p[(4*og+1)*128 + i],
                                p[(4*og+2)*128 + i], p[(4*og+3)*128 + i]);
    } else if (idx < 36864) {
        int e = idx - 24576;
        int n = e / 4096, rem = e % 4096, ig = rem / 128, o = rem % 128;
        const float* p = dw + n * 16384;
        g_dw4[e] = make_float4(p[(4*ig+0)*128 + o], p[(4*ig+1)*128 + o],
                               p[(4*ig+2)*128 + o], p[(4*ig+3)*128 + o]);
    } else if (idx < 49152) {
        int e = idx - 36864;
        int kg = e / 128, j = e % 128;
        g_aw4[e] = make_float4(aw[(4*kg+0)*128 + j], aw[(4*kg+1)*128 + j],
                               aw[(4*kg+2)*128 + j], aw[(4*kg+3)*128 + j]);
    }
}

// ---------------- parallel precompute of x-only terms ----------------------
// grid (TT, 6): w<3 -> GX cols w*128..w*128+127 ; w>=3 -> PX sub-layer n=w-3
__global__ void __launch_bounds__(256) precompute_kernel(
    const float* __restrict__ x, const float* __restrict__ K,
    const float* __restrict__ skx, const float* __restrict__ bias)
{
    __shared__ float4 xs4[BB * 32];                    // x[:,t,:] 64x128 = 32KB
    int t = blockIdx.x;
    int w = blockIdx.y;
    int tid = threadIdx.x;

    const float4* xg = (const float4*)x;
    #pragma unroll
    for (int q = tid; q < BB * 32; q += 256) {
        int bb = q >> 5, dq = q & 31;
        xs4[q] = xg[(size_t)(bb * TT + t) * 32 + dq];
    }
    __syncthreads();

    int jq = tid & 31;          // column quad: cols 4*jq..4*jq+3
    int bq = tid >> 5;          // row group: rows 8*bq..8*bq+7
    int c  = 4 * jq;
    const float* xsf = (const float*)xs4;

    const float* W;
    int wstride;
    if (w < 3) { W = K + w * 128 + c; wstride = G3; }
    else       { W = skx + (w - 3) * 16384 + c; wstride = 128; }

    float acc[8][4];
    #pragma unroll
    for (int bi = 0; bi < 8; bi++)
        #pragma unroll
        for (int q = 0; q < 4; q++) acc[bi][q] = 0.f;

    #pragma unroll 4
    for (int d = 0; d < 128; d++) {
        float4 wv = *(const float4*)(W + (size_t)d * wstride);
        #pragma unroll
        for (int bi = 0; bi < 8; bi++) {
            float xv = xsf[(8 * bq + bi) * 128 + d];
            acc[bi][0] = fmaf(xv, wv.x, acc[bi][0]);
            acc[bi][1] = fmaf(xv, wv.y, acc[bi][1]);
            acc[bi][2] = fmaf(xv, wv.z, acc[bi][2]);
            acc[bi][3] = fmaf(xv, wv.w, acc[bi][3]);
        }
    }

    if (w < 3) {
        float4 bv = *(const float4*)(bias + w * 128 + c);
        #pragma unroll
        for (int bi = 0; bi < 8; bi++) {
            int b = 8 * bq + bi;
            float4 r = make_float4(acc[bi][0] + bv.x, acc[bi][1] + bv.y,
                                   acc[bi][2] + bv.z, acc[bi][3] + bv.w);
            *(float4*)&g_GX[((size_t)t * BB + b) * G3 + w * 128 + c] = r;
        }
    } else {
        #pragma unroll
        for (int bi = 0; bi < 8; bi++) {
            int b = 8 * bq + bi;
            *(float4*)&g_PX[((size_t)t * (NS * BB) + (w - 3) * BB + b) * 128 + c] =
                make_float4(acc[bi][0], acc[bi][1], acc[bi][2], acc[bi][3]);
        }
    }
}

// ---------------- sequential recurrence: 64 independent chains -------------
struct SeqSmem {
    float4 aw[96 * 128];   // 196608 B, SMEM-resident agg_w
    float  h[128];
    float  g[G3];
    float  s[G3];
    float  agg[G3];
    float  sub[G3];
    float  db[G3];
    float  rh[G3];
    float  rx[G3];
    float  ab[128];
};

__device__ __forceinline__ float sigm(float v) { return 1.f / (1.f + expf(-v)); }

__global__ void __launch_bounds__(384, 1) seq_kernel(
    const float* __restrict__ stk, const float* __restrict__ db,
    const float* __restrict__ ab, float* __restrict__ out)
{
    extern __shared__ char smem_raw[];
    SeqSmem& sh = *reinterpret_cast<SeqSmem*>(smem_raw);

    int tid = threadIdx.x;
    int b   = blockIdx.x;
    int k   = tid >> 7;                 // 0..2 (which of the 3 owned s-rows)
    int col = tid & 127;
    int r   = 3 * b + k;                // owned row in (n*64+b2) space
    int n   = r >> 6;                   // sub-layer index (fixed over time)

    // init smem
    for (int i = tid; i < 96 * 128; i += 384) sh.aw[i] = g_aw4[i];
    sh.db[tid] = db[n * 128 + col];
    sh.rh[tid] = stk[n * 256 + col];
    sh.rx[tid] = stk[n * 256 + 128 + col];
    sh.s[tid]  = 0.f;
    sh.g[tid]  = 0.f;
    sh.agg[tid] = 0.f;
    sh.sub[tid] = 0.f;
    if (tid < 128) { sh.ab[tid] = ab[tid]; sh.h[tid] = 0.f; }
    float c_reg = 0.f;
    __syncthreads();

    const float4* Rp = g_R4 + tid;              // gates col = tid
    const float4* Sp = g_skh4 + n * 4096 + col; // agg col
    const float4* Dp = g_dw4  + n * 4096 + col; // dense col
    const float*  sk   = sh.s   + (k << 7);
    const float*  aggk = sh.agg + (k << 7);

    for (int t = 0; t < TT; t++) {
        // ---- stage 1 (gates) + stage 2 (agg_in): both read only h,s of prev step
        float gx = g_GX[((size_t)t * BB + b) * G3 + tid];
        float px = g_PX[((size_t)t * (NS * BB) + r) * 128 + col];

        float a0 = 0.f, a1 = 0.f, a2 = 0.f, a3 = 0.f;
        #pragma unroll 8
        for (int ug = 0; ug < 32; ug++) {
            float4 wv = Rp[ug * G3];
            a0 = fmaf(sh.h[4*ug+0], wv.x, a0);
            a1 = fmaf(sh.h[4*ug+1], wv.y, a1);
            a2 = fmaf(sh.h[4*ug+2], wv.z, a2);
            a3 = fmaf(sh.h[4*ug+3], wv.w, a3);
        }
        float gpre = gx + ((a0 + a1) + (a2 + a3));

        float e0 = 0.f, e1 = 0.f, e2 = 0.f, e3 = 0.f;
        #pragma unroll 8
        for (int og = 0; og < 32; og++) {
            float4 wv = Sp[og * 128];
            e0 = fmaf(sk[4*og+0], wv.x, e0);
            e1 = fmaf(sk[4*og+1], wv.y, e1);
            e2 = fmaf(sk[4*og+2], wv.z, e2);
            e3 = fmaf(sk[4*og+3], wv.w, e3);
        }
        sh.g[tid]   = sigm(gpre);
        sh.agg[tid] = px + ((e0 + e1) + (e2 + e3));
        __syncthreads();

        // ---- stage 3 (dense + relu, s update, c update)
        float d0 = 0.f, d1 = 0.f, d2 = 0.f, d3 = 0.f;
        #pragma unroll 8
        for (int ig = 0; ig < 32; ig++) {
            float4 wv = Dp[ig * 128];
            d0 = fmaf(aggk[4*ig+0], wv.x, d0);
            d1 = fmaf(aggk[4*ig+1], wv.y, d1);
            d2 = fmaf(aggk[4*ig+2], wv.z, d2);
            d3 = fmaf(aggk[4*ig+3], wv.w, d3);
        }
        float so = ((d0 + d1) + (d2 + d3)) + sh.db[tid];
        so = fmaxf(so, 0.f);
        sh.sub[tid] = so;
        sh.s[tid] = fmaf(sh.rh[tid], so, sh.rx[tid] * sh.s[tid]);
        if (tid < 128) {
            // c = f*c + i*tanh(cg) ; gates = [i | f | cg]
            c_reg = fmaf(sh.g[128 + tid], c_reg, sh.g[tid] * tanhf(sh.g[256 + tid]));
        }
        __syncthreads();

        // ---- stage 4 (output gate over flat(sub_o) @ agg_w, h update)
        if (tid < 128) {
            const float4* Ap = sh.aw + tid;
            float o0 = 0.f, o1 = 0.f, o2 = 0.f, o3 = 0.f;
            #pragma unroll 8
            for (int kg = 0; kg < 96; kg++) {
                float4 wv = Ap[kg * 128];
                o0 = fmaf(sh.sub[4*kg+0], wv.x, o0);
                o1 = fmaf(sh.sub[4*kg+1], wv.y, o1);
                o2 = fmaf(sh.sub[4*kg+2], wv.z, o2);
                o3 = fmaf(sh.sub[4*kg+3], wv.w, o3);
            }
            float ov = sigm(((o0 + o1) + (o2 + o3)) + sh.ab[tid]);
            float hv = ov * tanhf(c_reg);
            sh.h[tid] = hv;
            out[((size_t)b * TT + t) * 128 + tid] = hv;  // (B,T,U)
        }
        __syncthreads();
    }
}

// ---------------- launch ----------------------------------------------------
extern "C" void kernel_launch(void* const* d_in, const int* in_sizes, int n_in,
                              void* d_out, int out_size)
{
    const float* x    = (const float*)d_in[0];
    const float* K    = (const float*)d_in[1];
    const float* R    = (const float*)d_in[2];
    const float* bias = (const float*)d_in[3];
    const float* skx  = (const float*)d_in[4];
    const float* skh  = (const float*)d_in[5];
    const float* stk  = (const float*)d_in[6];
    const float* dw   = (const float*)d_in[7];
    const float* db   = (const float*)d_in[8];
    const float* aw   = (const float*)d_in[9];
    const float* ab   = (const float*)d_in[10];
    float* out = (float*)d_out;

    pack_weights<<<192, 256>>>(R, skh, dw, aw);

    dim3 pg(TT, 6);
    precompute_kernel<<<pg, 256>>>(x, K, skx, bias);

    cudaFuncSetAttribute(seq_kernel, cudaFuncAttributeMaxDynamicSharedMemorySize,
                         (int)sizeof(SeqSmem));
    seq_kernel<<<BB, 384, sizeof(SeqSmem)>>>(stk, db, ab, out);
}

// round 5
// speedup vs baseline: 1.0275x; 1.0275x over previous
#include <cuda_runtime.h>
#include <math.h>

#define BB 64
#define TT 2048
#define DD 128
#define UU 128
#define G3 384
#define NS 3

// ---------------- scratch (device globals: allocation-free) ----------------
__device__ float  g_GX[(size_t)TT * BB * G3];          // x@kernel + bias   [t][b][384]
__device__ float  g_PX[(size_t)TT * NS * BB * DD];     // x@sub_kernel_x    [t][r=n*64+b2][128]
__device__ float4 g_R4[32 * G3];                       // recurrent_kernel, packed over u
__device__ float4 g_skh4[NS * 32 * 128];               // sub_kernel_h, packed over o
__device__ float4 g_dw4[NS * 32 * 128];                // dense_w, packed over i
__device__ float4 g_aw4[96 * 128];                     // agg_w, packed over row ko

// ---------------- weight packing: reduction-major float4 layouts -----------
__global__ void pack_weights(const float* __restrict__ R,
                             const float* __restrict__ skh,
                             const float* __restrict__ dw,
                             const float* __restrict__ aw) {
    int idx = blockIdx.x * blockDim.x + threadIdx.x;
    if (idx < 12288) {
        int ug = idx / G3, j = idx % G3;
        g_R4[idx] = make_float4(R[(4*ug+0)*G3 + j], R[(4*ug+1)*G3 + j],
                                R[(4*ug+2)*G3 + j], R[(4*ug+3)*G3 + j]);
    } else if (idx < 24576) {
        int e = idx - 12288;
        int n = e / 4096, rem = e % 4096, og = rem / 128, i = rem % 128;
        const float* p = skh + n * 16384;
        g_skh4[e] = make_float4(p[(4*og+0)*128 + i], p[(4*og+1)*128 + i],
                                p[(4*og+2)*128 + i], p[(4*og+3)*128 + i]);
    } else if (idx < 36864) {
        int e = idx - 24576;
        int n = e / 4096, rem = e % 4096, ig = rem / 128, o = rem % 128;
        const float* p = dw + n * 16384;
        g_dw4[e] = make_float4(p[(4*ig+0)*128 + o], p[(4*ig+1)*128 + o],
                               p[(4*ig+2)*128 + o], p[(4*ig+3)*128 + o]);
    } else if (idx < 49152) {
        int e = idx - 36864;
        int kg = e / 128, j = e % 128;
        g_aw4[e] = make_float4(aw[(4*kg+0)*128 + j], aw[(4*kg+1)*128 + j],
                               aw[(4*kg+2)*128 + j], aw[(4*kg+3)*128 + j]);
    }
}

// ---------------- parallel precompute of x-only terms ----------------------
__global__ void __launch_bounds__(256) precompute_kernel(
    const float* __restrict__ x, const float* __restrict__ K,
    const float* __restrict__ skx, const float* __restrict__ bias)
{
    __shared__ float4 xs4[BB * 32];                    // x[:,t,:] 64x128 = 32KB
    int t = blockIdx.x;
    int w = blockIdx.y;
    int tid = threadIdx.x;

    const float4* xg = (const float4*)x;
    #pragma unroll
    for (int q = tid; q < BB * 32; q += 256) {
        int bb = q >> 5, dq = q & 31;
        xs4[q] = xg[(size_t)(bb * TT + t) * 32 + dq];
    }
    __syncthreads();

    int jq = tid & 31;
    int bq = tid >> 5;
    int c  = 4 * jq;
    const float* xsf = (const float*)xs4;

    const float* W;
    int wstride;
    if (w < 3) { W = K + w * 128 + c; wstride = G3; }
    else       { W = skx + (w - 3) * 16384 + c; wstride = 128; }

    float acc[8][4];
    #pragma unroll
    for (int bi = 0; bi < 8; bi++)
        #pragma unroll
        for (int q = 0; q < 4; q++) acc[bi][q] = 0.f;

    #pragma unroll 4
    for (int d = 0; d < 128; d++) {
        float4 wv = *(const float4*)(W + (size_t)d * wstride);
        #pragma unroll
        for (int bi = 0; bi < 8; bi++) {
            float xv = xsf[(8 * bq + bi) * 128 + d];
            acc[bi][0] = fmaf(xv, wv.x, acc[bi][0]);
            acc[bi][1] = fmaf(xv, wv.y, acc[bi][1]);
            acc[bi][2] = fmaf(xv, wv.z, acc[bi][2]);
            acc[bi][3] = fmaf(xv, wv.w, acc[bi][3]);
        }
    }

    if (w < 3) {
        float4 bv = *(const float4*)(bias + w * 128 + c);
        #pragma unroll
        for (int bi = 0; bi < 8; bi++) {
            int b = 8 * bq + bi;
            float4 r = make_float4(acc[bi][0] + bv.x, acc[bi][1] + bv.y,
                                   acc[bi][2] + bv.z, acc[bi][3] + bv.w);
            *(float4*)&g_GX[((size_t)t * BB + b) * G3 + w * 128 + c] = r;
        }
    } else {
        #pragma unroll
        for (int bi = 0; bi < 8; bi++) {
            int b = 8 * bq + bi;
            *(float4*)&g_PX[((size_t)t * (NS * BB) + (w - 3) * BB + b) * 128 + c] =
                make_float4(acc[bi][0], acc[bi][1], acc[bi][2], acc[bi][3]);
        }
    }
}

// ---------------- sequential recurrence: 64 independent chains -------------
struct SeqSmem {
    float4 aw[96 * 128];   // 196608 B, SMEM-resident agg_w
    float  h[128];
    float  g[G3];
    float  s[G3];
    float  agg[G3];
    float  sub[G3];
    float  part[G3];       // stage-4 split-K partials [k][col]
    float  db[G3];
    float  rh[G3];
    float  rx[G3];
    float  ab[128];
};

__device__ __forceinline__ float sigm_fast(float v) {
    return __fdividef(1.f, 1.f + __expf(-v));
}
__device__ __forceinline__ float tanh_fast(float v) {
    // 1 - 2/(e^{2v}+1); abs err ~1e-6 (MUFU EX2 + fast rcp), saturates correctly
    return 1.f - __fdividef(2.f, __expf(2.f * v) + 1.f);
}

__global__ void __launch_bounds__(384, 1) seq_kernel(
    const float* __restrict__ stk, const float* __restrict__ db,
    const float* __restrict__ ab, float* __restrict__ out)
{
    extern __shared__ char smem_raw[];
    SeqSmem& sh = *reinterpret_cast<SeqSmem*>(smem_raw);

    int tid = threadIdx.x;
    int b   = blockIdx.x;
    int k   = tid >> 7;                 // 0..2
    int col = tid & 127;
    int r   = 3 * b + k;                // owned row in (n*64+b2) space
    int n   = r >> 6;                   // sub-layer index (fixed over time)

    // init smem
    for (int i = tid; i < 96 * 128; i += 384) sh.aw[i] = g_aw4[i];
    sh.db[tid] = db[n * 128 + col];
    sh.rh[tid] = stk[n * 256 + col];
    sh.rx[tid] = stk[n * 256 + 128 + col];
    sh.s[tid]  = 0.f;
    sh.g[tid]  = 0.f;
    sh.agg[tid] = 0.f;
    sh.sub[tid] = 0.f;
    sh.part[tid] = 0.f;
    if (tid < 128) { sh.ab[tid] = ab[tid]; sh.h[tid] = 0.f; }
    float c_reg = 0.f, tc = 0.f;
    __syncthreads();

    const float4* Rp = g_R4 + tid;              // gates col = tid
    const float4* Sp = g_skh4 + n * 4096 + col; // agg col
    const float4* Dp = g_dw4  + n * 4096 + col; // dense col
    const float4* h4 = (const float4*)sh.h;
    const float4* s4 = (const float4*)(sh.s   + (k << 7));
    const float4* a4 = (const float4*)(sh.agg + (k << 7));
    const float4* b4 = (const float4*)(sh.sub + (k << 7));
    const float4* Ap = sh.aw + (k << 12) + col; // aw rows [128k,128k+128): quads 32k+q

    const float* gxp = g_GX + (size_t)b * G3 + tid;                 // stride BB*G3 per t
    const float* pxp = g_PX + (size_t)r * 128 + col;                // stride NS*BB*128 per t
    float gx = __ldcs(gxp);
    float px = __ldcs(pxp);

    for (int t = 0; t < TT; t++) {
        // prefetch next step's x-terms (covered by this whole step)
        int tn = (t + 1 < TT) ? (t + 1) : t;
        float gxN = __ldcs(gxp + (size_t)tn * (BB * G3));
        float pxN = __ldcs(pxp + (size_t)tn * (NS * BB * 128));

        // ---- stage 1 (gates) + stage 2 (agg_in)
        float a0 = 0.f, a1 = 0.f, a2 = 0.f, a3 = 0.f;
        #pragma unroll 8
        for (int ug = 0; ug < 32; ug++) {
            float4 wv = Rp[ug * G3];
            float4 hv = h4[ug];
            a0 = fmaf(hv.x, wv.x, a0);
            a1 = fmaf(hv.y, wv.y, a1);
            a2 = fmaf(hv.z, wv.z, a2);
            a3 = fmaf(hv.w, wv.w, a3);
        }
        float e0 = 0.f, e1 = 0.f, e2 = 0.f, e3 = 0.f;
        #pragma unroll 8
        for (int og = 0; og < 32; og++) {
            float4 wv = Sp[og * 128];
            float4 sv = s4[og];
            e0 = fmaf(sv.x, wv.x, e0);
            e1 = fmaf(sv.y, wv.y, e1);
            e2 = fmaf(sv.z, wv.z, e2);
            e3 = fmaf(sv.w, wv.w, e3);
        }
        sh.g[tid]   = sigm_fast(gx + ((a0 + a1) + (a2 + a3)));
        sh.agg[tid] = px + ((e0 + e1) + (e2 + e3));
        __syncthreads();

        // ---- stage 3 (dense + relu, s update, c update)
        float d0 = 0.f, d1 = 0.f, d2 = 0.f, d3 = 0.f;
        #pragma unroll 8
        for (int ig = 0; ig < 32; ig++) {
            float4 wv = Dp[ig * 128];
            float4 av = a4[ig];
            d0 = fmaf(av.x, wv.x, d0);
            d1 = fmaf(av.y, wv.y, d1);
            d2 = fmaf(av.z, wv.z, d2);
            d3 = fmaf(av.w, wv.w, d3);
        }
        float so = ((d0 + d1) + (d2 + d3)) + sh.db[tid];
        so = fmaxf(so, 0.f);
        sh.sub[tid] = so;
        sh.s[tid] = fmaf(sh.rh[tid], so, sh.rx[tid] * sh.s[tid]);
        if (tid < 128) {
            // c = f*c + i*tanh(cg); gates = [i | f | cg]
            c_reg = fmaf(sh.g[128 + tid], c_reg, sh.g[tid] * tanh_fast(sh.g[256 + tid]));
            tc = tanh_fast(c_reg);
        }
        __syncthreads();

        // ---- stage 4a: split-K over the 384-dim sub reduction (all threads)
        float o0 = 0.f, o1 = 0.f, o2 = 0.f, o3 = 0.f;
        #pragma unroll 8
        for (int q = 0; q < 32; q++) {
            float4 wv = Ap[q * 128];
            float4 sv = b4[q];
            o0 = fmaf(sv.x, wv.x, o0);
            o1 = fmaf(sv.y, wv.y, o1);
            o2 = fmaf(sv.z, wv.z, o2);
            o3 = fmaf(sv.w, wv.w, o3);
        }
        sh.part[tid] = (o0 + o1) + (o2 + o3);
        __syncthreads();

        // ---- stage 4b: combine partials, output gate, h update
        if (tid < 128) {
            float p = sh.part[tid] + sh.part[128 + tid] + sh.part[256 + tid];
            float ov = sigm_fast(p + sh.ab[tid]);
            float hv = ov * tc;
            sh.h[tid] = hv;
            __stcs(&out[((size_t)b * TT + t) * 128 + tid], hv);  // (B,T,U)
        }
        gx = gxN;
        px = pxN;
        __syncthreads();
    }
}

// ---------------- launch ----------------------------------------------------
extern "C" void kernel_launch(void* const* d_in, const int* in_sizes, int n_in,
                              void* d_out, int out_size)
{
    const float* x    = (const float*)d_in[0];
    const float* K    = (const float*)d_in[1];
    const float* R    = (const float*)d_in[2];
    const float* bias = (const float*)d_in[3];
    const float* skx  = (const float*)d_in[4];
    const float* skh  = (const float*)d_in[5];
    const float* stk  = (const float*)d_in[6];
    const float* dw   = (const float*)d_in[7];
    const float* db   = (const float*)d_in[8];
    const float* aw   = (const float*)d_in[9];
    const float* ab   = (const float*)d_in[10];
    float* out = (float*)d_out;

    pack_weights<<<192, 256>>>(R, skh, dw, aw);

    dim3 pg(TT, 6);
    precompute_kernel<<<pg, 256>>>(x, K, skx, bias);

    cudaFuncSetAttribute(seq_kernel, cudaFuncAttributeMaxDynamicSharedMemorySize,
                         (int)sizeof(SeqSmem));
    seq_kernel<<<BB, 384, sizeof(SeqSmem)>>>(stk, db, ab, out);
}

// round 7
// speedup vs baseline: 1.2262x; 1.1934x over previous
#include <cuda_runtime.h>
#include <cuda_fp16.h>
#include <math.h>

#define BB 64
#define TT 2048
#define DD 128
#define UU 128
#define G3 384
#define NS 3

// ---------------- scratch (device globals: allocation-free) ----------------
__device__ float   g_GX[(size_t)TT * BB * G3];      // x@kernel + bias   [t][b][384]
__device__ float   g_PX[(size_t)TT * NS * BB * DD]; // x@sub_kernel_x    [t][r][128]
__device__ __half2 g_Rh2[64 * G3];                  // R packed: [ug][j], u=2ug,2ug+1
__device__ __half2 g_skh2[NS * 64 * 128];           // skh packed: [n][og][i]
__device__ __half2 g_dwh2[NS * 64 * 128];           // dw packed:  [n][ig][o]
__device__ __half2 g_awh2[192 * 128];               // aw packed:  [kg][j]

// ---------------- weight packing: reduction-major half2 --------------------
__global__ void pack_weights(const float* __restrict__ R,
                             const float* __restrict__ skh,
                             const float* __restrict__ dw,
                             const float* __restrict__ aw) {
    int idx = blockIdx.x * blockDim.x + threadIdx.x;
    if (idx < 24576) {                      // R: 64 x 384
        int ug = idx / G3, j = idx % G3;
        g_Rh2[idx] = __floats2half2_rn(R[(2*ug)*G3 + j], R[(2*ug+1)*G3 + j]);
    } else if (idx < 49152) {               // skh: 3 x 64 x 128
        int e = idx - 24576;
        int n = e / 8192, rem = e % 8192, og = rem / 128, i = rem % 128;
        const float* p = skh + n * 16384;
        g_skh2[e] = __floats2half2_rn(p[(2*og)*128 + i], p[(2*og+1)*128 + i]);
    } else if (idx < 73728) {               // dw: 3 x 64 x 128
        int e = idx - 49152;
        int n = e / 8192, rem = e % 8192, ig = rem / 128, o = rem % 128;
        const float* p = dw + n * 16384;
        g_dwh2[e] = __floats2half2_rn(p[(2*ig)*128 + o], p[(2*ig+1)*128 + o]);
    } else if (idx < 98304) {               // aw: 192 x 128
        int e = idx - 73728;
        int kg = e / 128, j = e % 128;
        g_awh2[e] = __floats2half2_rn(aw[(2*kg)*128 + j], aw[(2*kg+1)*128 + j]);
    }
}

// ---------------- parallel precompute of x-only terms (fp32) ---------------
__global__ void __launch_bounds__(256) precompute_kernel(
    const float* __restrict__ x, const float* __restrict__ K,
    const float* __restrict__ skx, const float* __restrict__ bias)
{
    __shared__ float4 xs4[BB * 32];                    // x[:,t,:] 64x128 = 32KB
    int t = blockIdx.x;
    int w = blockIdx.y;
    int tid = threadIdx.x;

    const float4* xg = (const float4*)x;
    #pragma unroll
    for (int q = tid; q < BB * 32; q += 256) {
        int bb = q >> 5, dq = q & 31;
        xs4[q] = xg[(size_t)(bb * TT + t) * 32 + dq];
    }
    __syncthreads();

    int jq = tid & 31;
    int bq = tid >> 5;
    int c  = 4 * jq;
    const float* xsf = (const float*)xs4;

    const float* W;
    int wstride;
    if (w < 3) { W = K + w * 128 + c; wstride = G3; }
    else       { W = skx + (w - 3) * 16384 + c; wstride = 128; }

    float acc[8][4];
    #pragma unroll
    for (int bi = 0; bi < 8; bi++)
        #pragma unroll
        for (int q = 0; q < 4; q++) acc[bi][q] = 0.f;

    #pragma unroll 4
    for (int d = 0; d < 128; d++) {
        float4 wv = *(const float4*)(W + (size_t)d * wstride);
        #pragma unroll
        for (int bi = 0; bi < 8; bi++) {
            float xv = xsf[(8 * bq + bi) * 128 + d];
            acc[bi][0] = fmaf(xv, wv.x, acc[bi][0]);
            acc[bi][1] = fmaf(xv, wv.y, acc[bi][1]);
            acc[bi][2] = fmaf(xv, wv.z, acc[bi][2]);
            acc[bi][3] = fmaf(xv, wv.w, acc[bi][3]);
        }
    }

    if (w < 3) {
        float4 bv = *(const float4*)(bias + w * 128 + c);
        #pragma unroll
        for (int bi = 0; bi < 8; bi++) {
            int b = 8 * bq + bi;
            float4 r = make_float4(acc[bi][0] + bv.x, acc[bi][1] + bv.y,
                                   acc[bi][2] + bv.z, acc[bi][3] + bv.w);
            *(float4*)&g_GX[((size_t)t * BB + b) * G3 + w * 128 + c] = r;
        }
    } else {
        #pragma unroll
        for (int bi = 0; bi < 8; bi++) {
            int b = 8 * bq + bi;
            *(float4*)&g_PX[((size_t)t * (NS * BB) + (w - 3) * BB + b) * 128 + c] =
                make_float4(acc[bi][0], acc[bi][1], acc[bi][2], acc[bi][3]);
        }
    }
}

// ---------------- sequential recurrence: 64 independent chains -------------
struct __align__(16) SeqSmem {
    __half2 dw[NS * 64 * 128];   // 98304 B
    __half2 aw[192 * 128];       // 98304 B
    float   h[128];
    float   g[G3];
    float   s[G3];
    float   agg[G3];
    float   sub[G3];
    float   part[G3];
    float   db[G3];
    float   rh[G3];
    float   rx[G3];
    float   ab[128];
};

__device__ __forceinline__ float sigm_fast(float v) {
    return __fdividef(1.f, 1.f + __expf(-v));
}
__device__ __forceinline__ float tanh_fast(float v) {
    return 1.f - __fdividef(2.f, __expf(2.f * v) + 1.f);
}

__global__ void __launch_bounds__(384, 1) seq_kernel(
    const float* __restrict__ stk, const float* __restrict__ db,
    const float* __restrict__ ab, float* __restrict__ out)
{
    extern __shared__ char smem_raw[];
    SeqSmem& sh = *reinterpret_cast<SeqSmem*>(smem_raw);

    int tid = threadIdx.x;
    int b   = blockIdx.x;
    int k   = tid >> 7;                 // 0..2
    int col = tid & 127;
    int r   = 3 * b + k;                // owned row in (n*64+b2) space
    int n   = r >> 6;                   // sub-layer index (fixed over time)

    // init smem (weights via uint4 bulk copy)
    {
        const uint4* src_dw = (const uint4*)g_dwh2;
        const uint4* src_aw = (const uint4*)g_awh2;
        uint4* dst_dw = (uint4*)sh.dw;
        uint4* dst_aw = (uint4*)sh.aw;
        for (int i = tid; i < 24576 / 4; i += 384) {
            dst_dw[i] = src_dw[i];
            dst_aw[i] = src_aw[i];
        }
    }
    sh.db[tid] = db[n * 128 + col];
    sh.rh[tid] = stk[n * 256 + col];
    sh.rx[tid] = stk[n * 256 + 128 + col];
    sh.s[tid]  = 0.f;
    sh.g[tid]  = 0.f;
    sh.agg[tid] = 0.f;
    sh.sub[tid] = 0.f;
    sh.part[tid] = 0.f;
    if (tid < 128) { sh.ab[tid] = ab[tid]; sh.h[tid] = 0.f; }
    float c_reg = 0.f, tc = 0.f;
    __syncthreads();

    const __half2* Rp = g_Rh2 + tid;               // [ug][j=tid]
    const __half2* Sp = g_skh2 + n * 8192 + col;   // [og][i=col]
    const __half2* Dp = sh.dw  + n * 8192 + col;   // [ig][o=col]
    const __half2* Ap = sh.aw  + (k << 13) + col;  // kg = 64k + .., [kg][j=col]
    const float4* h4 = (const float4*)sh.h;
    const float4* s4 = (const float4*)(sh.s   + (k << 7));
    const float4* a4 = (const float4*)(sh.agg + (k << 7));
    const float4* b4 = (const float4*)(sh.sub + (k << 7));

    const float* gxp = g_GX + (size_t)b * G3 + tid;
    const float* pxp = g_PX + (size_t)r * 128 + col;
    float gx = __ldcs(gxp);
    float px = __ldcs(pxp);

    for (int t = 0; t < TT; t++) {
        int tn = (t + 1 < TT) ? (t + 1) : t;
        float gxN = __ldcs(gxp + (size_t)tn * (BB * G3));
        float pxN = __ldcs(pxp + (size_t)tn * (NS * BB * 128));

        // ---- stage 1 (gates) + stage 2 (agg_in): read prev-step h, s
        float a0 = 0.f, a1 = 0.f, a2 = 0.f, a3 = 0.f;
        #pragma unroll 8
        for (int u2 = 0; u2 < 32; u2++) {
            float4 hv = h4[u2];
            float2 w01 = __half22float2(Rp[(2*u2) * G3]);
            float2 w23 = __half22float2(Rp[(2*u2+1) * G3]);
            a0 = fmaf(hv.x, w01.x, a0);
            a1 = fmaf(hv.y, w01.y, a1);
            a2 = fmaf(hv.z, w23.x, a2);
            a3 = fmaf(hv.w, w23.y, a3);
        }
        float e0 = 0.f, e1 = 0.f, e2 = 0.f, e3 = 0.f;
        #pragma unroll 8
        for (int o2 = 0; o2 < 32; o2++) {
            float4 sv = s4[o2];
            float2 w01 = __half22float2(Sp[(2*o2) * 128]);
            float2 w23 = __half22float2(Sp[(2*o2+1) * 128]);
            e0 = fmaf(sv.x, w01.x, e0);
            e1 = fmaf(sv.y, w01.y, e1);
            e2 = fmaf(sv.z, w23.x, e2);
            e3 = fmaf(sv.w, w23.y, e3);
        }
        sh.g[tid]   = sigm_fast(gx + ((a0 + a1) + (a2 + a3)));
        sh.agg[tid] = px + ((e0 + e1) + (e2 + e3));
        __syncthreads();

        // ---- stage 3 (dense + relu, s update, c update)
        float d0 = 0.f, d1 = 0.f, d2 = 0.f, d3 = 0.f;
        #pragma unroll 8
        for (int i2 = 0; i2 < 32; i2++) {
            float4 av = a4[i2];
            float2 w01 = __half22float2(Dp[(2*i2) * 128]);
            float2 w23 = __half22float2(Dp[(2*i2+1) * 128]);
            d0 = fmaf(av.x, w01.x, d0);
            d1 = fmaf(av.y, w01.y, d1);
            d2 = fmaf(av.z, w23.x, d2);
            d3 = fmaf(av.w, w23.y, d3);
        }
        float so = ((d0 + d1) + (d2 + d3)) + sh.db[tid];
        so = fmaxf(so, 0.f);
        sh.sub[tid] = so;
        sh.s[tid] = fmaf(sh.rh[tid], so, sh.rx[tid] * sh.s[tid]);
        if (tid < 128) {
            c_reg = fmaf(sh.g[128 + tid], c_reg, sh.g[tid] * tanh_fast(sh.g[256 + tid]));
            tc = tanh_fast(c_reg);
        }
        __syncthreads();

        // ---- stage 4a: split-K over the 384-dim sub reduction (all threads)
        float o0 = 0.f, o1 = 0.f, o2 = 0.f, o3 = 0.f;
        #pragma unroll 8
        for (int q = 0; q < 32; q++) {
            float4 sv = b4[q];
            float2 w01 = __half22float2(Ap[(2*q) * 128]);
            float2 w23 = __half22float2(Ap[(2*q+1) * 128]);
            o0 = fmaf(sv.x, w01.x, o0);
            o1 = fmaf(sv.y, w01.y, o1);
            o2 = fmaf(sv.z, w23.x, o2);
            o3 = fmaf(sv.w, w23.y, o3);
        }
        sh.part[tid] = (o0 + o1) + (o2 + o3);
        __syncthreads();

        // ---- stage 4b: combine partials, output gate, h update
        if (tid < 128) {
            float p = sh.part[tid] + sh.part[128 + tid] + sh.part[256 + tid];
            float ov = sigm_fast(p + sh.ab[tid]);
            float hv = ov * tc;
            sh.h[tid] = hv;
            __stcs(&out[((size_t)b * TT + t) * 128 + tid], hv);  // (B,T,U)
        }
        gx = gxN;
        px = pxN;
        __syncthreads();
    }
}

// ---------------- launch ----------------------------------------------------
extern "C" void kernel_launch(void* const* d_in, const int* in_sizes, int n_in,
                              void* d_out, int out_size)
{
    const float* x    = (const float*)d_in[0];
    const float* K    = (const float*)d_in[1];
    const float* R    = (const float*)d_in[2];
    const float* bias = (const float*)d_in[3];
    const float* skx  = (const float*)d_in[4];
    const float* skh  = (const float*)d_in[5];
    const float* stk  = (const float*)d_in[6];
    const float* dw   = (const float*)d_in[7];
    const float* db   = (const float*)d_in[8];
    const float* aw   = (const float*)d_in[9];
    const float* ab   = (const float*)d_in[10];
    float* out = (float*)d_out;

    pack_weights<<<384, 256>>>(R, skh, dw, aw);

    dim3 pg(TT, 6);
    precompute_kernel<<<pg, 256>>>(x, K, skx, bias);

    cudaFuncSetAttribute(seq_kernel, cudaFuncAttributeMaxDynamicSharedMemorySize,
                         (int)sizeof(SeqSmem));
    seq_kernel<<<BB, 384, sizeof(SeqSmem)>>>(stk, db, ab, out);
}